// round 3
// baseline (speedup 1.0000x reference)
#include <cuda_runtime.h>

// Problem constants (B,H,S,D fixed by the dataset)
#define B_ 2
#define H_ 16
#define S_ 2048
#define DK 64
#define TQ 16          // query rows per CTA
#define TK 256         // key tile
#define NKT (S_ / TK)  // 8 key tiles
#define NTHREADS 256

// Dynamic SMEM layout (floats):
//   qT   [64][16]     : 1024     (Q tile, transposed: qT[d][r])
//   ks   [256][64]    : 16384    (K tile, per-row rotated; reused as V tile)
//   sc   [16][2048]   : 32768    (score strip; holds raw, then exp values)
//   rinv [16]         : 16       (1/rowsum)
#define SM_QT   0
#define SM_KS   1024
#define SM_SC   (1024 + 16384)
#define SM_RINV (1024 + 16384 + 32768)
#define SM_FLOATS (1024 + 16384 + 32768 + 16)
#define SM_BYTES (SM_FLOATS * 4)

extern "C" __global__ void __launch_bounds__(NTHREADS, 1)
attn_fused_kernel(const float* __restrict__ Q,
                  const float* __restrict__ K,
                  const float* __restrict__ V,
                  const int* __restrict__ mask,      // bool promoted to int32 by harness
                  float* __restrict__ ctx_out,
                  float* __restrict__ scores_out)
{
    extern __shared__ float smem[];
    float* qT   = smem + SM_QT;
    float* ks   = smem + SM_KS;
    float* sc   = smem + SM_SC;
    float* rinv = smem + SM_RINV;

    const int tid = threadIdx.x;
    const int bh  = blockIdx.z * H_ + blockIdx.y;
    const int q0  = blockIdx.x * TQ;

    const long long qbase = ((long long)bh * S_ + q0) * DK;   // Q / context base
    const long long mbase = ((long long)bh * S_ + q0) * S_;   // mask / scores base
    const long long kbase = (long long)bh * S_ * DK;          // K / V head base
    const float scale = 0.125f;                               // 1/sqrt(64)

    // ---- load Q tile (16x64), transposed into qT[d][r] ----
    #pragma unroll
    for (int i = 0; i < 4; i++) {
        int idx = tid + i * NTHREADS;       // 0..1023
        int r = idx >> 6, d = idx & 63;
        qT[d * 16 + r] = Q[qbase + idx];
    }

    const int ty = tid >> 6;   // 0..3  -> rows 4*ty .. 4*ty+3
    const int tx = tid & 63;   // 0..63 -> cols 4*tx .. 4*tx+3 (within k-tile)

    // ================= Phase 1: S = mask(QK^T * scale) into SMEM =================
    for (int kt = 0; kt < NKT; kt++) {
        __syncthreads();  // previous tile's ks reads are done
        // load FULL K tile (256x64 = 16384 floats = 4096 float4) with per-row
        // rotation: elem (c,d) -> c*64 + ((d + (c>>2)) & 63)
        const float4* Kg4 = (const float4*)(K + kbase + (long long)kt * TK * DK);
        #pragma unroll
        for (int i = 0; i < 16; i++) {
            int idx4 = tid + i * NTHREADS;      // 0..4095
            int c  = idx4 >> 4;                 // key row 0..255 (16 float4 per row)
            int d0 = (idx4 & 15) * 4;           // starting dim
            float4 v = Kg4[idx4];
            int rotbase = c >> 2;
            ks[c * 64 + ((d0 + 0 + rotbase) & 63)] = v.x;
            ks[c * 64 + ((d0 + 1 + rotbase) & 63)] = v.y;
            ks[c * 64 + ((d0 + 2 + rotbase) & 63)] = v.z;
            ks[c * 64 + ((d0 + 3 + rotbase) & 63)] = v.w;
        }
        __syncthreads();

        float acc[4][4];
        #pragma unroll
        for (int i = 0; i < 4; i++)
            #pragma unroll
            for (int u = 0; u < 4; u++) acc[i][u] = 0.0f;

        #pragma unroll 4
        for (int j = 0; j < DK; j++) {
            float4 qv = *(const float4*)&qT[j * 16 + 4 * ty];
            const float* qf = (const float*)&qv;
            // cols c = 4*tx+u, rotation index = (j + (c>>2)) & 63 = (j + tx) & 63 for u<4
            int rot = (j + tx) & 63;
            float kv0 = ks[(4 * tx + 0) * 64 + rot];
            float kv1 = ks[(4 * tx + 1) * 64 + rot];
            float kv2 = ks[(4 * tx + 2) * 64 + rot];
            float kv3 = ks[(4 * tx + 3) * 64 + rot];
            #pragma unroll
            for (int i = 0; i < 4; i++) {
                float qi = qf[i];
                acc[i][0] = fmaf(qi, kv0, acc[i][0]);
                acc[i][1] = fmaf(qi, kv1, acc[i][1]);
                acc[i][2] = fmaf(qi, kv2, acc[i][2]);
                acc[i][3] = fmaf(qi, kv3, acc[i][3]);
            }
        }

        // mask + scale, store raw scores strip
        #pragma unroll
        for (int i = 0; i < 4; i++) {
            int r = 4 * ty + i;
            int col = kt * TK + 4 * tx;
            int4 mk = *(const int4*)&mask[mbase + (long long)r * S_ + col];
            float4 o;
            o.x = mk.x ? -1e6f : acc[i][0] * scale;
            o.y = mk.y ? -1e6f : acc[i][1] * scale;
            o.z = mk.z ? -1e6f : acc[i][2] * scale;
            o.w = mk.w ? -1e6f : acc[i][3] * scale;
            *(float4*)&sc[r * S_ + col] = o;
        }
    }
    __syncthreads();

    // ================= Phase 2: row softmax (16 threads per row) =================
    {
        const int row = tid >> 4;
        const int l16 = tid & 15;
        float4* sc4 = (float4*)sc;

        float mx = -1e30f;
        #pragma unroll 8
        for (int m = 0; m < 32; m++) {
            float4 v = sc4[row * 512 + l16 + m * 16];
            mx = fmaxf(mx, fmaxf(fmaxf(v.x, v.y), fmaxf(v.z, v.w)));
        }
        #pragma unroll
        for (int o = 8; o > 0; o >>= 1)
            mx = fmaxf(mx, __shfl_xor_sync(0xffffffffu, mx, o));

        float sum = 0.0f;
        #pragma unroll 4
        for (int m = 0; m < 32; m++) {
            float4 v = sc4[row * 512 + l16 + m * 16];
            v.x = __expf(v.x - mx);
            v.y = __expf(v.y - mx);
            v.z = __expf(v.z - mx);
            v.w = __expf(v.w - mx);
            sum += (v.x + v.y) + (v.z + v.w);
            sc4[row * 512 + l16 + m * 16] = v;   // sc now holds exp values
        }
        #pragma unroll
        for (int o = 8; o > 0; o >>= 1)
            sum += __shfl_xor_sync(0xffffffffu, sum, o);
        if (l16 == 0) rinv[row] = 1.0f / sum;
    }
    __syncthreads();

    // ================= Phase 3: write normalized scores (coalesced) =================
    {
        float4* sc4 = (float4*)sc;
        float4* so4 = (float4*)(scores_out + mbase);   // 16x2048 contiguous strip
        #pragma unroll 4
        for (int it = 0; it < 32; it++) {
            int f4 = tid + it * NTHREADS;   // 0..8191
            float inv = rinv[f4 >> 9];      // row = f4/512
            float4 v = sc4[f4];
            v.x *= inv; v.y *= inv; v.z *= inv; v.w *= inv;
            so4[f4] = v;
        }
    }

    // ================= Phase 4: context = P @ V =================
    {
        const int pr = tid >> 4;    // row 0..15
        const int dq = tid & 15;    // d quad: d = 4*dq..4*dq+3
        float4 acc = make_float4(0.f, 0.f, 0.f, 0.f);
        float*  vs  = ks;           // reuse K tile buffer, natural layout [k][d]
        float4* vs4 = (float4*)vs;
        float4* sc4 = (float4*)sc;

        for (int kt = 0; kt < NKT; kt++) {
            __syncthreads();  // previous vs reads done / ks reads done on first iter
            // FULL V tile copy: 16384 floats = 4096 float4
            const float4* Vg4 = (const float4*)(V + kbase + (long long)kt * TK * DK);
            #pragma unroll
            for (int i = 0; i < 16; i++) {
                int idx4 = tid + i * NTHREADS;   // 0..4095
                vs4[idx4] = Vg4[idx4];
            }
            __syncthreads();

            #pragma unroll 2
            for (int jj = 0; jj < 64; jj++) {   // 4 keys per step
                float4 p = sc4[pr * 512 + kt * 64 + jj];
                float4 v;
                v = vs4[(4 * jj + 0) * 16 + dq];
                acc.x = fmaf(p.x, v.x, acc.x); acc.y = fmaf(p.x, v.y, acc.y);
                acc.z = fmaf(p.x, v.z, acc.z); acc.w = fmaf(p.x, v.w, acc.w);
                v = vs4[(4 * jj + 1) * 16 + dq];
                acc.x = fmaf(p.y, v.x, acc.x); acc.y = fmaf(p.y, v.y, acc.y);
                acc.z = fmaf(p.y, v.z, acc.z); acc.w = fmaf(p.y, v.w, acc.w);
                v = vs4[(4 * jj + 2) * 16 + dq];
                acc.x = fmaf(p.z, v.x, acc.x); acc.y = fmaf(p.z, v.y, acc.y);
                acc.z = fmaf(p.z, v.z, acc.z); acc.w = fmaf(p.z, v.w, acc.w);
                v = vs4[(4 * jj + 3) * 16 + dq];
                acc.x = fmaf(p.w, v.x, acc.x); acc.y = fmaf(p.w, v.y, acc.y);
                acc.z = fmaf(p.w, v.z, acc.z); acc.w = fmaf(p.w, v.w, acc.w);
            }
        }

        float inv = rinv[pr];
        float4 o = make_float4(acc.x * inv, acc.y * inv, acc.z * inv, acc.w * inv);
        *(float4*)&ctx_out[qbase + (long long)pr * DK + 4 * dq] = o;
    }
}

extern "C" void kernel_launch(void* const* d_in, const int* in_sizes, int n_in,
                              void* d_out, int out_size) {
    const float* Q = (const float*)d_in[0];
    const float* K = (const float*)d_in[1];
    const float* V = (const float*)d_in[2];
    const int* mask = (const int*)d_in[3];

    // Output tuple (context, scores): context [B,H,S,D] first, then scores [B,H,S,S]
    float* ctx = (float*)d_out;
    float* scores = (float*)d_out + (long long)B_ * H_ * S_ * DK;

    cudaFuncSetAttribute(attn_fused_kernel,
                         cudaFuncAttributeMaxDynamicSharedMemorySize, SM_BYTES);

    dim3 grid(S_ / TQ, H_, B_);   // (128, 16, 2)
    attn_fused_kernel<<<grid, NTHREADS, SM_BYTES>>>(Q, K, V, mask, ctx, scores);
}

// round 5
// speedup vs baseline: 3.4623x; 3.4623x over previous
#include <cuda_runtime.h>
#include <cuda_bf16.h>
#include <cstdint>

// Problem constants
#define B_ 2
#define H_ 16
#define S_ 2048
#define DKK 64
#define TQ 128           // query rows per CTA
#define TKEY 128         // key tile
#define NKT 16
#define NTH 256
#define PITCH 144        // smem row pitch in bytes (conflict-free ldmatrix)

// SMEM offsets (bytes): 6 tiles of 128 rows x 144B = 18432 each
#define SM_QHI 0
#define SM_QLO 18432
#define SM_KHI 36864
#define SM_KLO 55296
#define SM_VHI 73728
#define SM_VLO 92160
#define SM_TOTAL 110592

__device__ float g_rowsum_inv[B_ * H_ * S_];

__device__ __forceinline__ uint32_t smem_u32(const void* p) {
    uint32_t a;
    asm("{ .reg .u64 t; cvta.to.shared.u64 t, %1; cvt.u32.u64 %0, t; }" : "=r"(a) : "l"(p));
    return a;
}
__device__ __forceinline__ void ldsm_x4(uint32_t addr, uint32_t r[4]) {
    asm volatile("ldmatrix.sync.aligned.m8n8.x4.shared.b16 {%0,%1,%2,%3}, [%4];"
        : "=r"(r[0]), "=r"(r[1]), "=r"(r[2]), "=r"(r[3]) : "r"(addr));
}
__device__ __forceinline__ void ldsm_x2(uint32_t addr, uint32_t& r0, uint32_t& r1) {
    asm volatile("ldmatrix.sync.aligned.m8n8.x2.shared.b16 {%0,%1}, [%2];"
        : "=r"(r0), "=r"(r1) : "r"(addr));
}
__device__ __forceinline__ void ldsm_x2t(uint32_t addr, uint32_t& r0, uint32_t& r1) {
    asm volatile("ldmatrix.sync.aligned.m8n8.x2.trans.shared.b16 {%0,%1}, [%2];"
        : "=r"(r0), "=r"(r1) : "r"(addr));
}
__device__ __forceinline__ void mma_bf16(float c[4], const uint32_t a[4], uint32_t b0, uint32_t b1) {
    asm volatile("mma.sync.aligned.m16n8k16.row.col.f32.bf16.bf16.f32 "
        "{%0,%1,%2,%3},{%4,%5,%6,%7},{%8,%9},{%0,%1,%2,%3};"
        : "+f"(c[0]), "+f"(c[1]), "+f"(c[2]), "+f"(c[3])
        : "r"(a[0]), "r"(a[1]), "r"(a[2]), "r"(a[3]), "r"(b0), "r"(b1));
}

// split fp32 -> bf16 (hi) + bf16 (residual lo); pack 2 elems per .b32 (a low, b high)
__device__ __forceinline__ void split_pack(float a, float b, uint32_t& hw, uint32_t& lw) {
    __nv_bfloat16 ah = __float2bfloat16_rn(a);
    __nv_bfloat16 bh = __float2bfloat16_rn(b);
    __nv_bfloat16 al = __float2bfloat16_rn(a - __bfloat162float(ah));
    __nv_bfloat16 bl = __float2bfloat16_rn(b - __bfloat162float(bh));
    hw = ((uint32_t)__bfloat16_as_ushort(bh) << 16) | (uint32_t)__bfloat16_as_ushort(ah);
    lw = ((uint32_t)__bfloat16_as_ushort(bl) << 16) | (uint32_t)__bfloat16_as_ushort(al);
}

// Load 128x64 fp32 tile from gmem, split into bf16 hi/lo tiles (pitch 144B)
__device__ __forceinline__ void load_split(const float4* __restrict__ g4, char* smem,
                                           int ohi, int olo, int tid) {
    #pragma unroll
    for (int i = 0; i < 8; i++) {
        int idx4 = tid + i * NTH;            // 0..2047
        float4 v = g4[idx4];
        int row = idx4 >> 4;                 // 16 float4 per 64-elem row
        int d0  = (idx4 & 15) * 4;
        uint32_t wh0, wl0, wh1, wl1;
        split_pack(v.x, v.y, wh0, wl0);
        split_pack(v.z, v.w, wh1, wl1);
        int off = row * PITCH + d0 * 2;
        *(uint2*)(smem + ohi + off) = make_uint2(wh0, wh1);
        *(uint2*)(smem + olo + off) = make_uint2(wl0, wl1);
    }
}

extern "C" __global__ void __launch_bounds__(NTH, 1)
attn_mma_kernel(const float* __restrict__ Q, const float* __restrict__ K,
                const float* __restrict__ V, const int* __restrict__ mask,
                float* __restrict__ ctx_out, float* __restrict__ scores_out)
{
    extern __shared__ char smem[];
    const uint32_t sb = smem_u32(smem);
    const int tid  = threadIdx.x;
    const int wid  = tid >> 5;          // 0..7, owns q rows [16w, 16w+16)
    const int lane = tid & 31;
    const int g    = lane >> 2;         // row within 8-group
    const int q    = lane & 3;          // col pair selector

    const int bh = blockIdx.y;
    const int q0 = blockIdx.x * TQ;
    const size_t row0 = (size_t)bh * S_ + q0 + 16 * wid + g;   // global row (this thread)
    const size_t kvbase = (size_t)bh * S_ * DKK;

    // ---- stage Q tile (split bf16) ----
    load_split((const float4*)(Q + ((size_t)bh * S_ + q0) * DKK), smem, SM_QHI, SM_QLO, tid);
    __syncthreads();

    // ---- Q A-fragments, held in registers: 4 ksteps x 4 regs x (hi,lo) ----
    uint32_t qhi[4][4], qlo[4][4];
    {
        const uint32_t qrow = (uint32_t)(16 * wid + (lane & 15)) * PITCH + ((lane >> 4) & 1) * 16;
        #pragma unroll
        for (int s = 0; s < 4; s++) {
            ldsm_x4(sb + SM_QHI + qrow + 32 * s, qhi[s]);
            ldsm_x4(sb + SM_QLO + qrow + 32 * s, qlo[s]);
        }
    }

    float cacc[8][4];
    #pragma unroll
    for (int n = 0; n < 8; n++)
        #pragma unroll
        for (int e = 0; e < 4; e++) cacc[n][e] = 0.0f;
    float rsum0 = 0.0f, rsum1 = 0.0f;

    // per-lane ldmatrix address components
    const uint32_t kAddrBase = (uint32_t)(lane & 7) * PITCH + ((lane >> 3) & 1) * 16;  // K b-frags
    const uint32_t vAddrBase = (uint32_t)(lane & 15) * PITCH;                          // V b-frags (trans)

    uint32_t ahi[8][4], alo[8][4];      // P fragments for PV

    for (int kt = 0; kt < NKT; kt++) {
        __syncthreads();   // prior tile's smem reads complete
        load_split((const float4*)(K + kvbase + (size_t)kt * TKEY * DKK), smem, SM_KHI, SM_KLO, tid);
        load_split((const float4*)(V + kvbase + (size_t)kt * TKEY * DKK), smem, SM_VHI, SM_VLO, tid);
        __syncthreads();

        // ======== QK^T per 8-key block j, immediate epilogue ========
        #pragma unroll
        for (int j = 0; j < 16; j++) {
            float c[4] = {0.f, 0.f, 0.f, 0.f};
            #pragma unroll
            for (int s = 0; s < 4; s++) {
                uint32_t addr = (uint32_t)(8 * j) * PITCH + 32 * s + kAddrBase;
                uint32_t bh0, bh1, bl0, bl1;
                ldsm_x2(sb + SM_KHI + addr, bh0, bh1);
                ldsm_x2(sb + SM_KLO + addr, bl0, bl1);
                mma_bf16(c, qhi[s], bh0, bh1);
                mma_bf16(c, qhi[s], bl0, bl1);
                mma_bf16(c, qlo[s], bh0, bh1);
            }
            // mask + exp + store unnormalized scores + rowsum + repack as PV A-frags
            const int col = kt * TKEY + 8 * j + 2 * q;
            int2 m0 = *(const int2*)(mask + row0 * S_ + col);
            int2 m1 = *(const int2*)(mask + (row0 + 8) * S_ + col);
            float p0 = m0.x ? 0.0f : __expf(0.125f * c[0]);
            float p1 = m0.y ? 0.0f : __expf(0.125f * c[1]);
            float p2 = m1.x ? 0.0f : __expf(0.125f * c[2]);
            float p3 = m1.y ? 0.0f : __expf(0.125f * c[3]);
            rsum0 += p0 + p1;
            rsum1 += p2 + p3;
            *(float2*)(scores_out + row0 * S_ + col)       = make_float2(p0, p1);
            *(float2*)(scores_out + (row0 + 8) * S_ + col) = make_float2(p2, p3);
            uint32_t h01, l01, h23, l23;
            split_pack(p0, p1, h01, l01);
            split_pack(p2, p3, h23, l23);
            const int s2 = j >> 1, o = (j & 1) * 2;
            ahi[s2][o] = h01; ahi[s2][o + 1] = h23;
            alo[s2][o] = l01; alo[s2][o + 1] = l23;
        }

        // ======== PV: ctx += P @ V ========
        #pragma unroll
        for (int s = 0; s < 8; s++) {
            #pragma unroll
            for (int n = 0; n < 8; n++) {
                uint32_t addr = (uint32_t)(16 * s) * PITCH + 16 * n + vAddrBase;
                uint32_t bh0, bh1, bl0, bl1;
                ldsm_x2t(sb + SM_VHI + addr, bh0, bh1);
                ldsm_x2t(sb + SM_VLO + addr, bl0, bl1);
                mma_bf16(cacc[n], ahi[s], bh0, bh1);
                mma_bf16(cacc[n], ahi[s], bl0, bl1);
                mma_bf16(cacc[n], alo[s], bh0, bh1);
            }
        }
    }

    // ---- rowsum reduction over the 4 lanes of each quad ----
    #pragma unroll
    for (int o = 1; o < 4; o <<= 1) {
        rsum0 += __shfl_xor_sync(0xffffffffu, rsum0, o);
        rsum1 += __shfl_xor_sync(0xffffffffu, rsum1, o);
    }
    const float inv0 = 1.0f / rsum0;
    const float inv1 = 1.0f / rsum1;
    if (q == 0) {
        g_rowsum_inv[row0]     = inv0;
        g_rowsum_inv[row0 + 8] = inv1;
    }

    // ---- write context ----
    #pragma unroll
    for (int n = 0; n < 8; n++) {
        *(float2*)(ctx_out + row0 * DKK + 8 * n + 2 * q) =
            make_float2(cacc[n][0] * inv0, cacc[n][1] * inv0);
        *(float2*)(ctx_out + (row0 + 8) * DKK + 8 * n + 2 * q) =
            make_float2(cacc[n][2] * inv1, cacc[n][3] * inv1);
    }
}

// normalize scores in place: 512 float4 per row
extern "C" __global__ void __launch_bounds__(256)
norm_scores_kernel(float4* __restrict__ sc)
{
    size_t i = (size_t)blockIdx.x * 256 + threadIdx.x;
    float inv = g_rowsum_inv[i >> 9];
    float4 v = sc[i];
    v.x *= inv; v.y *= inv; v.z *= inv; v.w *= inv;
    sc[i] = v;
}

extern "C" void kernel_launch(void* const* d_in, const int* in_sizes, int n_in,
                              void* d_out, int out_size) {
    const float* Q = (const float*)d_in[0];
    const float* K = (const float*)d_in[1];
    const float* V = (const float*)d_in[2];
    const int* mask = (const int*)d_in[3];

    float* ctx    = (float*)d_out;
    float* scores = (float*)d_out + (long long)B_ * H_ * S_ * DKK;

    cudaFuncSetAttribute(attn_mma_kernel, cudaFuncAttributeMaxDynamicSharedMemorySize, SM_TOTAL);

    dim3 grid(S_ / TQ, B_ * H_);   // (16, 32)
    attn_mma_kernel<<<grid, NTH, SM_TOTAL>>>(Q, K, V, mask, ctx, scores);

    const long long n4 = (long long)B_ * H_ * S_ * S_ / 4;
    norm_scores_kernel<<<(unsigned)(n4 / 256), 256>>>((float4*)scores);
}